// round 10
// baseline (speedup 1.0000x reference)
#include <cuda_runtime.h>
#include <cstdint>

#define NF     12
#define NPAIR  66
#define NTRIP  220
#define NCOMB  781
#define NCOLS  793
#define NROWS  32768
#define WPB    8            // warps per block
#define RPW    2            // rows per warp
// slots: 0..11 s_i, 12 = 1.0, 16..81 = -pair, 82..301 = -triple
#define SLOT_P 16
#define SLOT_T 82
#define NVAL   304

typedef unsigned long long ull;

constexpr int pid(int i, int j) { return i * (2 * NF - i - 1) / 2 + (j - i - 1); }
constexpr int tid3(int I, int J, int K) {
    int p = 0;
    for (int i = 0; i < NF; ++i)
        for (int j = i + 1; j < NF; ++j)
            for (int k = j + 1; k < NF; ++k) {
                if (i == I && j == J && k == K) return p;
                ++p;
            }
    return -1;
}

// ---------------------------------------------------------------------------
// Tables of packed 16-bit BYTE offsets into val[NVAL][2] (8 B per slot).
// Main combo: q = fma(A, B, 1) with A from negated region, B from s/one.
// ---------------------------------------------------------------------------
struct CTbl { uint32_t v[NCOMB]; };
struct PTbl { uint32_t v[NPAIR]; };
struct TTbl { uint32_t v[NTRIP]; };

constexpr CTbl make_ctbl() {
    CTbl t{};
    int p = 0;
    for (int i = 0; i < NF; ++i)                    // pairs: (-P2)*1
        for (int j = i + 1; j < NF; ++j)
            t.v[p++] = (uint32_t)((SLOT_P + pid(i, j)) * 8)
                     | ((uint32_t)(12 * 8) << 16);
    for (int i = 0; i < NF; ++i)                    // triples: (-P2)*s_k
        for (int j = i + 1; j < NF; ++j)
            for (int k = j + 1; k < NF; ++k)
                t.v[p++] = (uint32_t)((SLOT_P + pid(i, j)) * 8)
                         | ((uint32_t)(k * 8) << 16);
    for (int i = 0; i < NF; ++i)                    // quads: (-P3)*s_l
        for (int j = i + 1; j < NF; ++j)
            for (int k = j + 1; k < NF; ++k)
                for (int l = k + 1; l < NF; ++l)
                    t.v[p++] = (uint32_t)((SLOT_T + tid3(i, j, k)) * 8)
                             | ((uint32_t)(l * 8) << 16);
    return t;
}
constexpr PTbl make_ptbl() {                        // pair build: s_i, s_j
    PTbl t{};
    int p = 0;
    for (int i = 0; i < NF; ++i)
        for (int j = i + 1; j < NF; ++j)
            t.v[p++] = (uint32_t)(i * 8) | ((uint32_t)(j * 8) << 16);
    return t;
}
constexpr TTbl make_ttbl() {                        // triple build: -P2(i,j), s_k
    TTbl t{};
    int p = 0;
    for (int i = 0; i < NF; ++i)
        for (int j = i + 1; j < NF; ++j)
            for (int k = j + 1; k < NF; ++k)
                t.v[p++] = (uint32_t)((SLOT_P + pid(i, j)) * 8)
                         | ((uint32_t)(k * 8) << 16);
    return t;
}

__device__ const CTbl d_ct = make_ctbl();
__device__ const PTbl d_pt = make_ptbl();
__device__ const TTbl d_tt = make_ttbl();

// ---- packed f32x2 helpers ---------------------------------------------------
__device__ __forceinline__ ull fma2(ull a, ull b, ull c) {
    ull d; asm("fma.rn.f32x2 %0,%1,%2,%3;" : "=l"(d) : "l"(a), "l"(b), "l"(c));
    return d;
}
__device__ __forceinline__ ull mul2(ull a, ull b) {
    ull d; asm("mul.rn.f32x2 %0,%1,%2;" : "=l"(d) : "l"(a), "l"(b));
    return d;
}
__device__ __forceinline__ ull pack2(float x, float y) {
    ull r;
    asm("mov.b64 %0,{%1,%2};" : "=l"(r)
        : "r"(__float_as_uint(x)), "r"(__float_as_uint(y)));
    return r;
}
__device__ __forceinline__ void unpack2(ull v, float& x, float& y) {
    uint32_t a, b;
    asm("mov.b64 {%0,%1},%2;" : "=r"(a), "=r"(b) : "l"(v));
    x = __uint_as_float(a); y = __uint_as_float(b);
}
__device__ __forceinline__ float lg2a(float x) {
    float r; asm("lg2.approx.f32 %0,%1;" : "=f"(r) : "f"(x)); return r;
}
__device__ __forceinline__ float ex2a(float x) {
    float r; asm("ex2.approx.f32 %0,%1;" : "=f"(r) : "f"(x)); return r;
}

// ---------------------------------------------------------------------------
__global__ __launch_bounds__(256)
void schweizer_kernel(const float* __restrict__ x,
                      const float* __restrict__ lam_p,
                      float* __restrict__ out)
{
    __shared__ __align__(8) float val[WPB][NVAL][RPW];

    const int lane = threadIdx.x & 31;
    const int wrp  = threadIdx.x >> 5;
    const int r0   = (blockIdx.x * WPB + wrp) * RPW;

    const float lam = __ldg(lam_p);
    const float inv = 1.0f / lam;

    const ull ONES = pack2(1.0f, 1.0f);
    const ull MN1  = pack2(-1.0f, -1.0f);
    const ull INV2 = pack2(inv, inv);

    float (*v)[RPW] = val[wrp];
    const char* vb = (const char*)v;

    // ---- prologue: s_i for 2 rows + passthrough ----------------------------
    if (lane < RPW * NF) {
        const float xv = x[(size_t)r0 * NF + lane];
        const int f = lane % NF, r = lane / NF;
        v[f][r] = 1.0f - __powf(1.0f - xv, lam);
        out[(size_t)(r0 + r) * NCOLS + f] = xv;
    } else if (lane < RPW * NF + RPW) {
        v[12][lane - RPW * NF] = 1.0f;                   // sentinel
    }
    __syncwarp();

    // ---- 66 negated pair products ------------------------------------------
    #pragma unroll
    for (int p = lane; p < NPAIR; p += 32) {
        const uint32_t w = d_pt.v[p];
        const float2 a = *(const float2*)(vb + (w & 0xFFFFu));
        const float2 b = *(const float2*)(vb + (w >> 16));
        float2 n2;
        n2.x = -(a.x * b.x);
        n2.y = -(a.y * b.y);
        *(float2*)v[SLOT_P + p] = n2;
    }
    __syncwarp();

    // ---- 220 negated triple products: -t = (-p) * s ------------------------
    #pragma unroll
    for (int t = lane; t < NTRIP; t += 32) {
        const uint32_t w = d_tt.v[t];
        const float2 np = *(const float2*)(vb + (w & 0xFFFFu));
        const float2 s2 = *(const float2*)(vb + (w >> 16));
        float2 n2;
        n2.x = np.x * s2.x;
        n2.y = np.y * s2.y;
        *(float2*)v[SLOT_T + t] = n2;
    }
    __syncwarp();

    // ---- main sweep: 24 full 32-column groups + 13-column tail -------------
    float* __restrict__ o0 = out + (size_t)r0 * NCOLS + NF;
    float* __restrict__ o1 = o0 + NCOLS;

    #pragma unroll 4
    for (int k = 0; k < 24; ++k) {
        const int c = k * 32 + lane;
        const uint32_t w = d_ct.v[c];
        const ull A = *(const ull*)(vb + (w & 0xFFFFu));  // (-a0, -a1) random slot
        const ull B = *(const ull*)(vb + (w >> 16));      // 13-slot region: N=1
        const ull Q = fma2(A, B, ONES);                   // 1 - a*b (both rows)
        float q0, q1; unpack2(Q, q0, q1);
        const ull M = mul2(pack2(lg2a(q0), lg2a(q1)), INV2);
        float m0, m1; unpack2(M, m0, m1);
        const ull R = fma2(pack2(ex2a(m0), ex2a(m1)), MN1, ONES); // 1 - q^inv
        float r0v, r1v; unpack2(R, r0v, r1v);
        o0[c] = r0v;
        o1[c] = r1v;
    }
    if (lane < NCOMB - 768) {                             // cols 768..780
        const int c = 768 + lane;
        const uint32_t w = d_ct.v[c];
        const float* pa = (const float*)(vb + (w & 0xFFFFu));
        const float* pb = (const float*)(vb + (w >> 16));
        const float q0 = fmaf(pa[0], pb[0], 1.0f);
        const float q1 = fmaf(pa[1], pb[1], 1.0f);
        o0[c] = 1.0f - ex2a(lg2a(q0) * inv);
        o1[c] = 1.0f - ex2a(lg2a(q1) * inv);
    }
}

extern "C" void kernel_launch(void* const* d_in, const int* in_sizes, int n_in,
                              void* d_out, int out_size)
{
    const float* x   = (const float*)d_in[0];
    const float* lam = (const float*)d_in[1];
    float*       out = (float*)d_out;

    schweizer_kernel<<<NROWS / (WPB * RPW), 256>>>(x, lam, out);
}